// round 1
// baseline (speedup 1.0000x reference)
#include <cuda_runtime.h>
#include <cuda_bf16.h>
#include <math.h>

// Problem constants (fixed by the reference setup)
#define D_MODEL 1024
#define N_HEADS 16
#define D_HEAD  64
#define T_SEQ   2048
#define M_MAX   (4 * 2048)   // B*T

// ---------------- scratch (device globals; no allocation allowed) -------------
__device__ float g_Q[(size_t)M_MAX * D_MODEL];
__device__ float g_K[(size_t)M_MAX * D_MODEL];
__device__ float g_V[(size_t)M_MAX * D_MODEL];
__device__ float g_Z[(size_t)M_MAX * D_MODEL];

// ---------------- GEMM: C[M,N] = A[M,K] @ B[K,N], fp32, 128x128x8 tiles -------
#define BM 128
#define BN 128
#define BKK 8

__global__ __launch_bounds__(256)
void gemm128(const float* __restrict__ A, const float* __restrict__ B,
             float* __restrict__ C, int M, int N, int K) {
    __shared__ float As[BKK][BM + 4];   // +4 pad -> stride 132 (conflict-free transpose store)
    __shared__ float Bs[BKK][BN];

    const int tid = threadIdx.x;           // 256 threads
    const int tx  = tid & 15;              // 0..15 (n tile)
    const int ty  = tid >> 4;              // 0..15 (m tile)
    const int rowBase = blockIdx.y * BM;
    const int colBase = blockIdx.x * BN;

    // A tile loader: 128 rows x 8 cols = 256 float4
    const int arow = tid >> 1;             // 0..127
    const int acol = (tid & 1) * 4;        // 0 or 4
    // B tile loader: 8 rows x 128 cols = 256 float4
    const int brow = tid >> 5;             // 0..7
    const int bcol = (tid & 31) * 4;       // 0..124

    const float* Aptr = A + (size_t)(rowBase + arow) * K + acol;
    const float* Bptr = B + (size_t)brow * N + colBase + bcol;

    float acc[8][8];
    #pragma unroll
    for (int i = 0; i < 8; i++)
        #pragma unroll
        for (int j = 0; j < 8; j++) acc[i][j] = 0.f;

    for (int k0 = 0; k0 < K; k0 += BKK) {
        float4 av = *(const float4*)(Aptr + k0);
        float4 bv = *(const float4*)(Bptr + (size_t)k0 * N);
        As[acol + 0][arow] = av.x;
        As[acol + 1][arow] = av.y;
        As[acol + 2][arow] = av.z;
        As[acol + 3][arow] = av.w;
        *(float4*)&Bs[brow][bcol] = bv;
        __syncthreads();

        #pragma unroll
        for (int kk = 0; kk < BKK; kk++) {
            float4 a0 = *(const float4*)&As[kk][ty * 8];
            float4 a1 = *(const float4*)&As[kk][ty * 8 + 4];
            float4 b0 = *(const float4*)&Bs[kk][tx * 8];
            float4 b1 = *(const float4*)&Bs[kk][tx * 8 + 4];
            float a[8] = {a0.x, a0.y, a0.z, a0.w, a1.x, a1.y, a1.z, a1.w};
            float b[8] = {b0.x, b0.y, b0.z, b0.w, b1.x, b1.y, b1.z, b1.w};
            #pragma unroll
            for (int i = 0; i < 8; i++)
                #pragma unroll
                for (int j = 0; j < 8; j++)
                    acc[i][j] = fmaf(a[i], b[j], acc[i][j]);
        }
        __syncthreads();
    }

    #pragma unroll
    for (int i = 0; i < 8; i++) {
        const int r = rowBase + ty * 8 + i;
        float4* cp = (float4*)(C + (size_t)r * N + colBase + tx * 8);
        cp[0] = make_float4(acc[i][0], acc[i][1], acc[i][2], acc[i][3]);
        cp[1] = make_float4(acc[i][4], acc[i][5], acc[i][6], acc[i][7]);
    }
}

// ---------------- Flash attention (causal), fp32 ------------------------------
// Layout: Q/K/V/Z are [B*T, 1024] where column = h*64 + d.
// One thread = one query row. Block = 128 queries of one (b,h).
#define BQ 128
#define BK2 32

__global__ __launch_bounds__(128)
void flash_attn(const float* __restrict__ Qg, const float* __restrict__ Kg,
                const float* __restrict__ Vg, float* __restrict__ Zg) {
    const int bh = blockIdx.y;
    const int b  = bh >> 4;            // / N_HEADS
    const int h  = bh & 15;
    // reverse query-tile order: heavy (high-q0) blocks launch first
    const int qt = gridDim.x - 1 - blockIdx.x;
    const int q0 = qt * BQ;
    const int tid = threadIdx.x;
    const int q = q0 + tid;

    const size_t bT   = (size_t)b * T_SEQ;
    const int    hoff = h * D_HEAD;

    // Q row in registers
    float qr[D_HEAD];
    {
        const float4* qp = (const float4*)(Qg + (bT + q) * D_MODEL + hoff);
        #pragma unroll
        for (int i = 0; i < 16; i++) {
            float4 v4 = qp[i];
            qr[4*i+0] = v4.x; qr[4*i+1] = v4.y; qr[4*i+2] = v4.z; qr[4*i+3] = v4.w;
        }
    }

    __shared__ float Ks[BK2][D_HEAD];
    __shared__ float Vs[BK2][D_HEAD];

    float o[D_HEAD];
    #pragma unroll
    for (int d = 0; d < D_HEAD; d++) o[d] = 0.f;
    float m = -1e30f;
    float l = 0.f;

    const int kend = q0 + BQ;  // max key count needed by any query in this block
    for (int kt = 0; kt < kend; kt += BK2) {
        // cooperative K/V tile load: 32x64 floats each = 512 float4 each
        #pragma unroll
        for (int it = 0; it < 4; it++) {
            int idx = tid + it * 128;            // 0..511
            int row = idx >> 4;                  // 0..31
            int col = (idx & 15) << 2;           // 0..60
            size_t g = (bT + kt + row) * D_MODEL + hoff + col;
            *(float4*)&Ks[row][col] = *(const float4*)(Kg + g);
            *(float4*)&Vs[row][col] = *(const float4*)(Vg + g);
        }
        __syncthreads();

        // scores for this tile
        float s[BK2];
        #pragma unroll
        for (int kk = 0; kk < BK2; kk++) {
            const float4* kp = (const float4*)Ks[kk];
            float acc = 0.f;
            #pragma unroll
            for (int i = 0; i < 16; i++) {
                float4 kv = kp[i];
                acc = fmaf(qr[4*i+0], kv.x, acc);
                acc = fmaf(qr[4*i+1], kv.y, acc);
                acc = fmaf(qr[4*i+2], kv.z, acc);
                acc = fmaf(qr[4*i+3], kv.w, acc);
            }
            s[kk] = ((kt + kk) <= q) ? acc * 0.125f : -1e30f;
        }

        // online softmax update
        float tmax = m;
        #pragma unroll
        for (int kk = 0; kk < BK2; kk++) tmax = fmaxf(tmax, s[kk]);
        if (tmax > m) {
            float alpha = __expf(m - tmax);
            m = tmax;
            l *= alpha;
            #pragma unroll
            for (int d = 0; d < D_HEAD; d++) o[d] *= alpha;
        }

        #pragma unroll
        for (int kk = 0; kk < BK2; kk++) {
            float p = __expf(s[kk] - m);
            l += p;
            const float4* vp = (const float4*)Vs[kk];
            #pragma unroll
            for (int i = 0; i < 16; i++) {
                float4 vv = vp[i];
                o[4*i+0] = fmaf(p, vv.x, o[4*i+0]);
                o[4*i+1] = fmaf(p, vv.y, o[4*i+1]);
                o[4*i+2] = fmaf(p, vv.z, o[4*i+2]);
                o[4*i+3] = fmaf(p, vv.w, o[4*i+3]);
            }
        }
        __syncthreads();
    }

    const float inv = 1.0f / l;
    float* zp = Zg + (bT + q) * D_MODEL + hoff;
    #pragma unroll
    for (int i = 0; i < 16; i++) {
        float4 v4 = make_float4(o[4*i+0]*inv, o[4*i+1]*inv, o[4*i+2]*inv, o[4*i+3]*inv);
        *(float4*)(zp + 4*i) = v4;
    }
}

// ---------------- launch -------------------------------------------------------
extern "C" void kernel_launch(void* const* d_in, const int* in_sizes, int n_in,
                              void* d_out, int out_size) {
    const float* x  = (const float*)d_in[0];
    const float* WQ = (const float*)d_in[1];
    const float* WK = (const float*)d_in[2];
    const float* WV = (const float*)d_in[3];
    const float* WO = (const float*)d_in[4];
    float* out = (float*)d_out;

    const int M = in_sizes[0] / D_MODEL;    // B*T = 8192
    const int Bb = M / T_SEQ;               // 4

    void *pQ, *pK, *pV, *pZ;
    cudaGetSymbolAddress(&pQ, g_Q);
    cudaGetSymbolAddress(&pK, g_K);
    cudaGetSymbolAddress(&pV, g_V);
    cudaGetSymbolAddress(&pZ, g_Z);

    dim3 gg(D_MODEL / BN, M / BM);   // (8, 64)
    gemm128<<<gg, 256>>>(x, WQ, (float*)pQ, M, D_MODEL, D_MODEL);
    gemm128<<<gg, 256>>>(x, WK, (float*)pK, M, D_MODEL, D_MODEL);
    gemm128<<<gg, 256>>>(x, WV, (float*)pV, M, D_MODEL, D_MODEL);

    dim3 fg(T_SEQ / BQ, Bb * N_HEADS);  // (16, 64)
    flash_attn<<<fg, 128>>>((const float*)pQ, (const float*)pK,
                            (const float*)pV, (float*)pZ);

    gemm128<<<gg, 256>>>((const float*)pZ, WO, out, M, D_MODEL, D_MODEL);
}

// round 3
// speedup vs baseline: 1.3849x; 1.3849x over previous
#include <cuda_runtime.h>
#include <cuda_bf16.h>
#include <cstdint>
#include <math.h>

#define D_MODEL 1024
#define N_HEADS 16
#define D_HEAD  64
#define T_SEQ   2048
#define M_ROWS  8192

typedef __nv_bfloat16 bf16;

// ---------------- scratch (device globals; no allocation allowed) -------------
__device__ float g_Q[(size_t)M_ROWS * D_MODEL];
__device__ float g_K[(size_t)M_ROWS * D_MODEL];
__device__ float g_V[(size_t)M_ROWS * D_MODEL];
__device__ bf16  g_xhi[(size_t)M_ROWS * D_MODEL];
__device__ bf16  g_xlo[(size_t)M_ROWS * D_MODEL];
__device__ bf16  g_wthi[4][(size_t)D_MODEL * D_MODEL];   // W^T, [N][K]
__device__ bf16  g_wtlo[4][(size_t)D_MODEL * D_MODEL];
__device__ bf16  g_zhi[(size_t)M_ROWS * D_MODEL];
__device__ bf16  g_zlo[(size_t)M_ROWS * D_MODEL];

// ---------------- PTX helpers (arch-neutral: sm_80-era, valid on compute_103) --
__device__ __forceinline__ uint32_t smem_u32(const void* p) {
    uint32_t a;
    asm("{ .reg .u64 t; cvta.to.shared.u64 t, %1; cvt.u32.u64 %0, t; }" : "=r"(a) : "l"(p));
    return a;
}
__device__ __forceinline__ void cp16(uint32_t dst, const void* src) {
    asm volatile("cp.async.cg.shared.global [%0], [%1], 16;" :: "r"(dst), "l"(src) : "memory");
}
__device__ __forceinline__ void cp_commit() { asm volatile("cp.async.commit_group;" ::: "memory"); }
__device__ __forceinline__ void cp_wait1()  { asm volatile("cp.async.wait_group 1;" ::: "memory"); }
__device__ __forceinline__ void cp_wait0()  { asm volatile("cp.async.wait_group 0;" ::: "memory"); }

__device__ __forceinline__ void ldm_x4(uint32_t* r, uint32_t addr) {
    asm volatile("ldmatrix.sync.aligned.m8n8.x4.shared.b16 {%0,%1,%2,%3}, [%4];"
                 : "=r"(r[0]), "=r"(r[1]), "=r"(r[2]), "=r"(r[3]) : "r"(addr));
}
__device__ __forceinline__ void ldm_x2(uint32_t* r, uint32_t addr) {
    asm volatile("ldmatrix.sync.aligned.m8n8.x2.shared.b16 {%0,%1}, [%2];"
                 : "=r"(r[0]), "=r"(r[1]) : "r"(addr));
}
__device__ __forceinline__ void mma_bf16(float* c, const uint32_t* a, const uint32_t* b) {
    asm volatile(
        "mma.sync.aligned.m16n8k16.row.col.f32.bf16.bf16.f32 "
        "{%0,%1,%2,%3}, {%4,%5,%6,%7}, {%8,%9}, {%0,%1,%2,%3};"
        : "+f"(c[0]), "+f"(c[1]), "+f"(c[2]), "+f"(c[3])
        : "r"(a[0]), "r"(a[1]), "r"(a[2]), "r"(a[3]), "r"(b[0]), "r"(b[1]));
}

// swizzled smem offset within one 128x32-bf16 chunk (row = 64B = 4 x 16B segs)
__device__ __forceinline__ uint32_t swz(int row, int kseg) {
    return (uint32_t)(row * 64 + ((kseg ^ ((row >> 1) & 3)) << 4));
}

// ---------------- mma.sync split-bf16 GEMM -------------------------------------
// C[M,1024] = A @ B^T, A = Ahi+Alo row-major [M][K], Bt = Bhi+Blo [N][K].
// 3-term product (hi*hi + hi*lo + lo*hi), fp32 accumulate.
#define KC 32
#define NCH (D_MODEL / KC)          // 32
#define MATB (128 * KC * 2)         // 8192 B per matrix chunk
#define STAGE (4 * MATB)            // 32768
#define DYN_SMEM (2 * STAGE)        // 65536

__global__ __launch_bounds__(256)
void gemm_mma(const bf16* __restrict__ Ahi, const bf16* __restrict__ Alo,
              const bf16* __restrict__ Bhi, const bf16* __restrict__ Blo,
              float* __restrict__ C) {
    extern __shared__ char dyn[];
    const uint32_t base = smem_u32(dyn);

    const int tid = threadIdx.x;
    const int wid = tid >> 5;
    const int lane = tid & 31;
    const int rowBase = blockIdx.y * 128;
    const int colBase = blockIdx.x * 128;

    // warp tile: 64x32 ; wm in {0,1}, wn in {0..3}
    const int wm = wid & 1;
    const int wn = wid >> 1;

    // loader mapping: 2 iters x 256 threads cover 128 rows x 4 segs per matrix
    const int l_seg = tid & 3;
    const int l_row0 = tid >> 2;    // 0..63

    auto load_chunk = [&](int c, int s) {
        const uint32_t sb = base + s * STAGE;
        const size_t kof = (size_t)c * KC + l_seg * 8;
        #pragma unroll
        for (int it = 0; it < 2; it++) {
            const int row = l_row0 + it * 64;
            const uint32_t so = swz(row, l_seg);
            const size_t aoff = (size_t)(rowBase + row) * D_MODEL + kof;
            const size_t boff = (size_t)(colBase + row) * D_MODEL + kof;
            cp16(sb + 0 * MATB + so, Ahi + aoff);
            cp16(sb + 1 * MATB + so, Alo + aoff);
            cp16(sb + 2 * MATB + so, Bhi + boff);
            cp16(sb + 3 * MATB + so, Blo + boff);
        }
        cp_commit();
    };

    float acc[4][4][4];
    #pragma unroll
    for (int i = 0; i < 4; i++)
        #pragma unroll
        for (int j = 0; j < 4; j++)
            #pragma unroll
            for (int k = 0; k < 4; k++) acc[i][j][k] = 0.f;

    // per-lane ldmatrix row/seg components
    const int g  = lane >> 3;       // 0..3
    const int lr = lane & 7;
    // A: lanes 0-7 rows+0 k0 | 8-15 rows+8 k0 | 16-23 rows+0 k8 | 24-31 rows+8 k8
    const int a_rofs = lr + (g & 1) * 8;
    const int a_kofs = g >> 1;      // 0 or 1 (16B seg within k-step)
    // B: lanes 0-7 n-rows k0 | 8-15 n-rows k8 (x2; upper lanes unused but valid)
    const int b_rofs = lr;
    const int b_kofs = g & 1;

    load_chunk(0, 0);
    load_chunk(1, 1);

    for (int c = 0; c < NCH; c++) {
        cp_wait1();
        __syncthreads();
        const uint32_t sb = base + (c & 1) * STAGE;

        #pragma unroll
        for (int ks = 0; ks < 2; ks++) {
            uint32_t ah[4][4], al[4][4], bh[4][2], bl[4][2];
            #pragma unroll
            for (int mt = 0; mt < 4; mt++) {
                const int row = wm * 64 + mt * 16 + a_rofs;
                const uint32_t so = swz(row, ks * 2 + a_kofs);
                ldm_x4(ah[mt], sb + 0 * MATB + so);
                ldm_x4(al[mt], sb + 1 * MATB + so);
            }
            #pragma unroll
            for (int nt = 0; nt < 4; nt++) {
                const int row = wn * 32 + nt * 8 + b_rofs;
                const uint32_t so = swz(row, ks * 2 + b_kofs);
                ldm_x2(bh[nt], sb + 2 * MATB + so);
                ldm_x2(bl[nt], sb + 3 * MATB + so);
            }
            #pragma unroll
            for (int mt = 0; mt < 4; mt++)
                #pragma unroll
                for (int nt = 0; nt < 4; nt++) {
                    mma_bf16(acc[mt][nt], ah[mt], bh[nt]);
                    mma_bf16(acc[mt][nt], ah[mt], bl[nt]);
                    mma_bf16(acc[mt][nt], al[mt], bh[nt]);
                }
        }

        __syncthreads();               // all warps done reading stage (c&1)
        if (c + 2 < NCH) load_chunk(c + 2, c & 1);
    }

    // epilogue: fragment -> gmem fp32 (thread t: rows q/4 & +8, cols (t%4)*2)
    const int er = lane >> 2;
    const int ec = (lane & 3) * 2;
    #pragma unroll
    for (int mt = 0; mt < 4; mt++) {
        const int r0 = rowBase + wm * 64 + mt * 16 + er;
        #pragma unroll
        for (int nt = 0; nt < 4; nt++) {
            const int cc = colBase + wn * 32 + nt * 8 + ec;
            float2* p0 = (float2*)(C + (size_t)r0 * D_MODEL + cc);
            float2* p1 = (float2*)(C + (size_t)(r0 + 8) * D_MODEL + cc);
            *p0 = make_float2(acc[mt][nt][0], acc[mt][nt][1]);
            *p1 = make_float2(acc[mt][nt][2], acc[mt][nt][3]);
        }
    }
}

// ---------------- decompose fp32 -> (hi, lo) bf16 ------------------------------
__global__ __launch_bounds__(256)
void decomp_kernel(const float* __restrict__ X, bf16* __restrict__ hi,
                   bf16* __restrict__ lo, int n4) {
    int i = blockIdx.x * 256 + threadIdx.x;
    if (i >= n4) return;
    float4 v = ((const float4*)X)[i];
    __nv_bfloat162 h0, h1, l0, l1;
    h0.x = __float2bfloat16(v.x); h0.y = __float2bfloat16(v.y);
    h1.x = __float2bfloat16(v.z); h1.y = __float2bfloat16(v.w);
    l0.x = __float2bfloat16(v.x - __bfloat162float(h0.x));
    l0.y = __float2bfloat16(v.y - __bfloat162float(h0.y));
    l1.x = __float2bfloat16(v.z - __bfloat162float(h1.x));
    l1.y = __float2bfloat16(v.w - __bfloat162float(h1.y));
    ((__nv_bfloat162*)hi)[2 * i]     = h0;
    ((__nv_bfloat162*)hi)[2 * i + 1] = h1;
    ((__nv_bfloat162*)lo)[2 * i]     = l0;
    ((__nv_bfloat162*)lo)[2 * i + 1] = l1;
}

// ---------------- transpose + decompose W[K][N] -> Wt hi/lo [N][K] -------------
__global__ __launch_bounds__(256)
void transdec_kernel(const float* __restrict__ W, bf16* __restrict__ thi,
                     bf16* __restrict__ tlo) {
    __shared__ float t[32][33];
    const int n0 = blockIdx.x * 32, k0 = blockIdx.y * 32;
    const int tx = threadIdx.x, ty0 = threadIdx.y;   // (32, 8)
    #pragma unroll
    for (int j = 0; j < 32; j += 8) {
        const int ty = ty0 + j;
        t[ty][tx] = W[(size_t)(k0 + ty) * D_MODEL + n0 + tx];
    }
    __syncthreads();
    #pragma unroll
    for (int j = 0; j < 32; j += 8) {
        const int ty = ty0 + j;
        const float v = t[tx][ty];   // = W[k0+tx][n0+ty]
        bf16 h = __float2bfloat16(v);
        const size_t o = (size_t)(n0 + ty) * D_MODEL + k0 + tx;
        thi[o] = h;
        tlo[o] = __float2bfloat16(v - __bfloat162float(h));
    }
}

// ---------------- Flash attention (causal), fp32, split-bf16 Z output ----------
#define BQ 128
#define BK2 32

__global__ __launch_bounds__(128)
void flash_attn(const float* __restrict__ Qg, const float* __restrict__ Kg,
                const float* __restrict__ Vg, bf16* __restrict__ Zhi,
                bf16* __restrict__ Zlo) {
    const int bh = blockIdx.y;
    const int b  = bh >> 4;
    const int h  = bh & 15;
    const int qt = gridDim.x - 1 - blockIdx.x;   // heavy tiles first
    const int q0 = qt * BQ;
    const int tid = threadIdx.x;
    const int q = q0 + tid;

    const size_t bT   = (size_t)b * T_SEQ;
    const int    hoff = h * D_HEAD;

    float qr[D_HEAD];
    {
        const float4* qp = (const float4*)(Qg + (bT + q) * D_MODEL + hoff);
        #pragma unroll
        for (int i = 0; i < 16; i++) {
            float4 v4 = qp[i];
            qr[4*i+0] = v4.x; qr[4*i+1] = v4.y; qr[4*i+2] = v4.z; qr[4*i+3] = v4.w;
        }
    }

    __shared__ float Ks[BK2][D_HEAD];
    __shared__ float Vs[BK2][D_HEAD];

    float o[D_HEAD];
    #pragma unroll
    for (int d = 0; d < D_HEAD; d++) o[d] = 0.f;
    float m = -1e30f;
    float l = 0.f;

    const int kend = q0 + BQ;
    for (int kt = 0; kt < kend; kt += BK2) {
        #pragma unroll
        for (int it = 0; it < 4; it++) {
            int idx = tid + it * 128;
            int row = idx >> 4;
            int col = (idx & 15) << 2;
            size_t gix = (bT + kt + row) * D_MODEL + hoff + col;
            *(float4*)&Ks[row][col] = *(const float4*)(Kg + gix);
            *(float4*)&Vs[row][col] = *(const float4*)(Vg + gix);
        }
        __syncthreads();

        float s[BK2];
        #pragma unroll
        for (int kk = 0; kk < BK2; kk++) {
            const float4* kp = (const float4*)Ks[kk];
            float a = 0.f;
            #pragma unroll
            for (int i = 0; i < 16; i++) {
                float4 kv = kp[i];
                a = fmaf(qr[4*i+0], kv.x, a);
                a = fmaf(qr[4*i+1], kv.y, a);
                a = fmaf(qr[4*i+2], kv.z, a);
                a = fmaf(qr[4*i+3], kv.w, a);
            }
            s[kk] = ((kt + kk) <= q) ? a * 0.125f : -1e30f;
        }

        float tmax = m;
        #pragma unroll
        for (int kk = 0; kk < BK2; kk++) tmax = fmaxf(tmax, s[kk]);
        if (tmax > m) {
            float alpha = __expf(m - tmax);
            m = tmax;
            l *= alpha;
            #pragma unroll
            for (int d = 0; d < D_HEAD; d++) o[d] *= alpha;
        }

        #pragma unroll
        for (int kk = 0; kk < BK2; kk++) {
            float p = __expf(s[kk] - m);
            l += p;
            const float4* vp = (const float4*)Vs[kk];
            #pragma unroll
            for (int i = 0; i < 16; i++) {
                float4 vv = vp[i];
                o[4*i+0] = fmaf(p, vv.x, o[4*i+0]);
                o[4*i+1] = fmaf(p, vv.y, o[4*i+1]);
                o[4*i+2] = fmaf(p, vv.z, o[4*i+2]);
                o[4*i+3] = fmaf(p, vv.w, o[4*i+3]);
            }
        }
        __syncthreads();
    }

    const float inv = 1.0f / l;
    bf16* zh = Zhi + (bT + q) * D_MODEL + hoff;
    bf16* zl = Zlo + (bT + q) * D_MODEL + hoff;
    #pragma unroll
    for (int d = 0; d < D_HEAD; d += 2) {
        float v0 = o[d] * inv, v1 = o[d + 1] * inv;
        __nv_bfloat162 h2, l2;
        h2.x = __float2bfloat16(v0);
        h2.y = __float2bfloat16(v1);
        l2.x = __float2bfloat16(v0 - __bfloat162float(h2.x));
        l2.y = __float2bfloat16(v1 - __bfloat162float(h2.y));
        *(__nv_bfloat162*)(zh + d) = h2;
        *(__nv_bfloat162*)(zl + d) = l2;
    }
}

// ---------------- launch --------------------------------------------------------
extern "C" void kernel_launch(void* const* d_in, const int* in_sizes, int n_in,
                              void* d_out, int out_size) {
    const float* x  = (const float*)d_in[0];
    const float* W[4] = {(const float*)d_in[1], (const float*)d_in[2],
                         (const float*)d_in[3], (const float*)d_in[4]};
    float* out = (float*)d_out;

    void *pQ, *pK, *pV, *pxh, *pxl, *pwh, *pwl, *pzh, *pzl;
    cudaGetSymbolAddress(&pQ, g_Q);
    cudaGetSymbolAddress(&pK, g_K);
    cudaGetSymbolAddress(&pV, g_V);
    cudaGetSymbolAddress(&pxh, g_xhi);
    cudaGetSymbolAddress(&pxl, g_xlo);
    cudaGetSymbolAddress(&pwh, g_wthi);
    cudaGetSymbolAddress(&pwl, g_wtlo);
    cudaGetSymbolAddress(&pzh, g_zhi);
    cudaGetSymbolAddress(&pzl, g_zlo);

    bf16* xhi = (bf16*)pxh;  bf16* xlo = (bf16*)pxl;
    bf16* zhi = (bf16*)pzh;  bf16* zlo = (bf16*)pzl;
    const size_t wstride = (size_t)D_MODEL * D_MODEL;

    cudaFuncSetAttribute(gemm_mma, cudaFuncAttributeMaxDynamicSharedMemorySize, DYN_SMEM);

    const int n4 = M_ROWS * D_MODEL / 4;
    decomp_kernel<<<(n4 + 255) / 256, 256>>>(x, xhi, xlo, n4);
    dim3 tg(D_MODEL / 32, D_MODEL / 32);
    for (int w = 0; w < 4; w++)
        transdec_kernel<<<tg, dim3(32, 8)>>>(W[w], (bf16*)pwh + w * wstride,
                                             (bf16*)pwl + w * wstride);

    dim3 gg(D_MODEL / 128, M_ROWS / 128);   // (8, 64)
    gemm_mma<<<gg, 256, DYN_SMEM>>>(xhi, xlo, (bf16*)pwh + 0 * wstride,
                                    (bf16*)pwl + 0 * wstride, (float*)pQ);
    gemm_mma<<<gg, 256, DYN_SMEM>>>(xhi, xlo, (bf16*)pwh + 1 * wstride,
                                    (bf16*)pwl + 1 * wstride, (float*)pK);
    gemm_mma<<<gg, 256, DYN_SMEM>>>(xhi, xlo, (bf16*)pwh + 2 * wstride,
                                    (bf16*)pwl + 2 * wstride, (float*)pV);

    dim3 fg(T_SEQ / BQ, (M_ROWS / T_SEQ) * N_HEADS);   // (16, 64)
    flash_attn<<<fg, 128>>>((const float*)pQ, (const float*)pK,
                            (const float*)pV, zhi, zlo);

    gemm_mma<<<gg, 256, DYN_SMEM>>>(zhi, zlo, (bf16*)pwh + 3 * wstride,
                                    (bf16*)pwl + 3 * wstride, out);
}

// round 4
// speedup vs baseline: 3.8029x; 2.7460x over previous
#include <cuda_runtime.h>
#include <cuda_bf16.h>
#include <cstdint>
#include <math.h>

#define D_MODEL 1024
#define N_HEADS 16
#define D_HEAD  64
#define T_SEQ   2048
#define M_ROWS  8192

typedef __nv_bfloat16 bf16;

// ---------------- scratch (device globals; no allocation allowed) -------------
__device__ bf16 g_xhi[(size_t)M_ROWS * D_MODEL];
__device__ bf16 g_xlo[(size_t)M_ROWS * D_MODEL];
__device__ bf16 g_wthi[4][(size_t)D_MODEL * D_MODEL];   // W^T, [N][K]
__device__ bf16 g_wtlo[4][(size_t)D_MODEL * D_MODEL];
__device__ bf16 g_qhi[(size_t)M_ROWS * D_MODEL];
__device__ bf16 g_qlo[(size_t)M_ROWS * D_MODEL];
__device__ bf16 g_khi[(size_t)M_ROWS * D_MODEL];
__device__ bf16 g_klo[(size_t)M_ROWS * D_MODEL];
__device__ bf16 g_vhi[(size_t)M_ROWS * D_MODEL];
__device__ bf16 g_vlo[(size_t)M_ROWS * D_MODEL];
__device__ bf16 g_zhi[(size_t)M_ROWS * D_MODEL];
__device__ bf16 g_zlo[(size_t)M_ROWS * D_MODEL];

// ---------------- PTX helpers (sm_80-era, valid on compute_103) ----------------
__device__ __forceinline__ uint32_t smem_u32(const void* p) {
    uint32_t a;
    asm("{ .reg .u64 t; cvta.to.shared.u64 t, %1; cvt.u32.u64 %0, t; }" : "=r"(a) : "l"(p));
    return a;
}
__device__ __forceinline__ void cp16(uint32_t dst, const void* src) {
    asm volatile("cp.async.cg.shared.global [%0], [%1], 16;" :: "r"(dst), "l"(src) : "memory");
}
__device__ __forceinline__ void cp_commit() { asm volatile("cp.async.commit_group;" ::: "memory"); }
__device__ __forceinline__ void cp_wait0()  { asm volatile("cp.async.wait_group 0;" ::: "memory"); }
__device__ __forceinline__ void cp_wait1()  { asm volatile("cp.async.wait_group 1;" ::: "memory"); }
__device__ __forceinline__ void cp_wait2()  { asm volatile("cp.async.wait_group 2;" ::: "memory"); }

__device__ __forceinline__ void ldm_x4(uint32_t* r, uint32_t addr) {
    asm volatile("ldmatrix.sync.aligned.m8n8.x4.shared.b16 {%0,%1,%2,%3}, [%4];"
                 : "=r"(r[0]), "=r"(r[1]), "=r"(r[2]), "=r"(r[3]) : "r"(addr));
}
__device__ __forceinline__ void ldm_x4t(uint32_t* r, uint32_t addr) {
    asm volatile("ldmatrix.sync.aligned.m8n8.x4.trans.shared.b16 {%0,%1,%2,%3}, [%4];"
                 : "=r"(r[0]), "=r"(r[1]), "=r"(r[2]), "=r"(r[3]) : "r"(addr));
}
__device__ __forceinline__ void ldm_x2(uint32_t* r, uint32_t addr) {
    asm volatile("ldmatrix.sync.aligned.m8n8.x2.shared.b16 {%0,%1}, [%2];"
                 : "=r"(r[0]), "=r"(r[1]) : "r"(addr));
}
__device__ __forceinline__ void mma_bf16(float* c, const uint32_t* a, const uint32_t* b) {
    asm volatile(
        "mma.sync.aligned.m16n8k16.row.col.f32.bf16.bf16.f32 "
        "{%0,%1,%2,%3}, {%4,%5,%6,%7}, {%8,%9}, {%0,%1,%2,%3};"
        : "+f"(c[0]), "+f"(c[1]), "+f"(c[2]), "+f"(c[3])
        : "r"(a[0]), "r"(a[1]), "r"(a[2]), "r"(a[3]), "r"(b[0]), "r"(b[1]));
}
__device__ __forceinline__ float shfl_xor_f(float v, int m) {
    return __shfl_xor_sync(0xFFFFFFFF, v, m);
}
// pack two fp32 -> hi bf16x2 + residual lo bf16x2
__device__ __forceinline__ void pack_hl(float x, float y, uint32_t& h, uint32_t& l) {
    __nv_bfloat162 hh = __floats2bfloat162_rn(x, y);
    __nv_bfloat162 ll = __floats2bfloat162_rn(x - __bfloat162float(hh.x),
                                              y - __bfloat162float(hh.y));
    h = *(uint32_t*)&hh;
    l = *(uint32_t*)&ll;
}

// ---------------- mma.sync split-bf16 GEMM -------------------------------------
// C = A @ B^T, A = Ahi+Alo [M][K], Bt = Bhi+Blo [N][K]. 3-term, fp32 accum.
// Output: fp32 C (if Chi==null) or hi/lo bf16 pair.
#define KC 32
#define NCHG (D_MODEL / KC)         // 32
#define MATB (128 * KC * 2)         // 8192 B
#define STAGE (4 * MATB)            // 32768
#define DYN_SMEM_G (2 * STAGE)      // 65536

__device__ __forceinline__ uint32_t swz64(int row, int kseg) {   // 64B rows, 4 segs
    return (uint32_t)(row * 64 + ((kseg ^ ((row >> 1) & 3)) << 4));
}

__global__ __launch_bounds__(256)
void gemm_mma(const bf16* __restrict__ Ahi, const bf16* __restrict__ Alo,
              const bf16* __restrict__ Bhi, const bf16* __restrict__ Blo,
              float* __restrict__ C, bf16* __restrict__ Chi, bf16* __restrict__ Clo) {
    extern __shared__ char dyn[];
    const uint32_t base = smem_u32(dyn);

    const int tid = threadIdx.x;
    const int wid = tid >> 5;
    const int lane = tid & 31;
    const int rowBase = blockIdx.y * 128;
    const int colBase = blockIdx.x * 128;
    const int wm = wid & 1;
    const int wn = wid >> 1;

    const int l_seg = tid & 3;
    const int l_row0 = tid >> 2;

    auto load_chunk = [&](int c, int s) {
        const uint32_t sb = base + s * STAGE;
        const size_t kof = (size_t)c * KC + l_seg * 8;
        #pragma unroll
        for (int it = 0; it < 2; it++) {
            const int row = l_row0 + it * 64;
            const uint32_t so = swz64(row, l_seg);
            const size_t aoff = (size_t)(rowBase + row) * D_MODEL + kof;
            const size_t boff = (size_t)(colBase + row) * D_MODEL + kof;
            cp16(sb + 0 * MATB + so, Ahi + aoff);
            cp16(sb + 1 * MATB + so, Alo + aoff);
            cp16(sb + 2 * MATB + so, Bhi + boff);
            cp16(sb + 3 * MATB + so, Blo + boff);
        }
        cp_commit();
    };

    float acc[4][4][4];
    #pragma unroll
    for (int i = 0; i < 4; i++)
        #pragma unroll
        for (int j = 0; j < 4; j++)
            #pragma unroll
            for (int k = 0; k < 4; k++) acc[i][j][k] = 0.f;

    const int g  = lane >> 3;
    const int lr = lane & 7;
    const int a_rofs = lr + (g & 1) * 8;
    const int a_kofs = g >> 1;
    const int b_rofs = lr;
    const int b_kofs = g & 1;

    load_chunk(0, 0);
    load_chunk(1, 1);

    for (int c = 0; c < NCHG; c++) {
        cp_wait1();
        __syncthreads();
        const uint32_t sb = base + (c & 1) * STAGE;

        #pragma unroll
        for (int ks = 0; ks < 2; ks++) {
            uint32_t ah[4][4], al[4][4], bh[4][2], bl[4][2];
            #pragma unroll
            for (int mt = 0; mt < 4; mt++) {
                const int row = wm * 64 + mt * 16 + a_rofs;
                const uint32_t so = swz64(row, ks * 2 + a_kofs);
                ldm_x4(ah[mt], sb + 0 * MATB + so);
                ldm_x4(al[mt], sb + 1 * MATB + so);
            }
            #pragma unroll
            for (int nt = 0; nt < 4; nt++) {
                const int row = wn * 32 + nt * 8 + b_rofs;
                const uint32_t so = swz64(row, ks * 2 + b_kofs);
                ldm_x2(bh[nt], sb + 2 * MATB + so);
                ldm_x2(bl[nt], sb + 3 * MATB + so);
            }
            #pragma unroll
            for (int mt = 0; mt < 4; mt++)
                #pragma unroll
                for (int nt = 0; nt < 4; nt++) {
                    mma_bf16(acc[mt][nt], ah[mt], bh[nt]);
                    mma_bf16(acc[mt][nt], ah[mt], bl[nt]);
                    mma_bf16(acc[mt][nt], al[mt], bh[nt]);
                }
        }

        __syncthreads();
        if (c + 2 < NCHG) load_chunk(c + 2, c & 1);
    }

    const int er = lane >> 2;
    const int ec = (lane & 3) * 2;
    if (Chi == nullptr) {
        #pragma unroll
        for (int mt = 0; mt < 4; mt++) {
            const int r0 = rowBase + wm * 64 + mt * 16 + er;
            #pragma unroll
            for (int nt = 0; nt < 4; nt++) {
                const int cc = colBase + wn * 32 + nt * 8 + ec;
                *(float2*)(C + (size_t)r0 * D_MODEL + cc) =
                    make_float2(acc[mt][nt][0], acc[mt][nt][1]);
                *(float2*)(C + (size_t)(r0 + 8) * D_MODEL + cc) =
                    make_float2(acc[mt][nt][2], acc[mt][nt][3]);
            }
        }
    } else {
        #pragma unroll
        for (int mt = 0; mt < 4; mt++) {
            const int r0 = rowBase + wm * 64 + mt * 16 + er;
            #pragma unroll
            for (int nt = 0; nt < 4; nt++) {
                const int cc = colBase + wn * 32 + nt * 8 + ec;
                uint32_t h0, l0, h1, l1;
                pack_hl(acc[mt][nt][0], acc[mt][nt][1], h0, l0);
                pack_hl(acc[mt][nt][2], acc[mt][nt][3], h1, l1);
                *(uint32_t*)(Chi + (size_t)r0 * D_MODEL + cc) = h0;
                *(uint32_t*)(Clo + (size_t)r0 * D_MODEL + cc) = l0;
                *(uint32_t*)(Chi + (size_t)(r0 + 8) * D_MODEL + cc) = h1;
                *(uint32_t*)(Clo + (size_t)(r0 + 8) * D_MODEL + cc) = l1;
            }
        }
    }
}

// ---------------- decompose fp32 -> (hi, lo) bf16 ------------------------------
__global__ __launch_bounds__(256)
void decomp_kernel(const float* __restrict__ X, bf16* __restrict__ hi,
                   bf16* __restrict__ lo, int n4) {
    int i = blockIdx.x * 256 + threadIdx.x;
    if (i >= n4) return;
    float4 v = ((const float4*)X)[i];
    uint32_t h0, l0, h1, l1;
    pack_hl(v.x, v.y, h0, l0);
    pack_hl(v.z, v.w, h1, l1);
    ((uint32_t*)hi)[2 * i]     = h0;
    ((uint32_t*)hi)[2 * i + 1] = h1;
    ((uint32_t*)lo)[2 * i]     = l0;
    ((uint32_t*)lo)[2 * i + 1] = l1;
}

// ---------------- transpose + decompose W[K][N] -> Wt hi/lo [N][K] -------------
__global__ __launch_bounds__(256)
void transdec_kernel(const float* __restrict__ W, bf16* __restrict__ thi,
                     bf16* __restrict__ tlo) {
    __shared__ float t[32][33];
    const int n0 = blockIdx.x * 32, k0 = blockIdx.y * 32;
    const int tx = threadIdx.x, ty0 = threadIdx.y;
    #pragma unroll
    for (int j = 0; j < 32; j += 8)
        t[ty0 + j][tx] = W[(size_t)(k0 + ty0 + j) * D_MODEL + n0 + tx];
    __syncthreads();
    #pragma unroll
    for (int j = 0; j < 32; j += 8) {
        const int ty = ty0 + j;
        const float v = t[tx][ty];
        bf16 h = __float2bfloat16(v);
        const size_t o = (size_t)(n0 + ty) * D_MODEL + k0 + tx;
        thi[o] = h;
        tlo[o] = __float2bfloat16(v - __bfloat162float(h));
    }
}

// ---------------- tensor-core flash attention (causal, split-bf16) -------------
// CTA: 64 queries of one (b,h); 4 warps x 16 rows. Key tiles of 64.
// smem: Qhi/Qlo 8KB each @0/8192; KV stages @16384: per stage Khi,Klo,Vhi,Vlo 8KB each.
#define FSTG 32768
#define DYN_SMEM_F (16384 + 2 * FSTG)

__device__ __forceinline__ uint32_t swz128(int row, int seg) {   // 128B rows, 8 segs
    return (uint32_t)(row * 128 + ((seg ^ (row & 7)) << 4));
}

__global__ __launch_bounds__(128)
void flash_tc(const bf16* __restrict__ Qhi, const bf16* __restrict__ Qlo,
              const bf16* __restrict__ Khi, const bf16* __restrict__ Klo,
              const bf16* __restrict__ Vhi, const bf16* __restrict__ Vlo,
              bf16* __restrict__ Zhi, bf16* __restrict__ Zlo) {
    extern __shared__ char dyn[];
    const uint32_t base = smem_u32(dyn);
    const uint32_t sQh = base, sQl = base + 8192;
    const uint32_t sKV = base + 16384;

    const int bh = blockIdx.y;
    const int b  = bh >> 4;
    const int h  = bh & 15;
    const int qt = gridDim.x - 1 - blockIdx.x;   // heavy CTAs first
    const int q0 = qt * 64;
    const int tid = threadIdx.x;
    const int wid = tid >> 5;
    const int lane = tid & 31;

    const size_t rowbase = (size_t)b * T_SEQ;
    const int hoff = h * D_HEAD;

    // ---- async loads ----
    const int l_seg = tid & 7, l_r0 = tid >> 3;   // 8 segs x 16 rows
    {   // Q tile (rows q0..q0+63)
        #pragma unroll
        for (int it = 0; it < 4; it++) {
            const int row = l_r0 + it * 16;
            const uint32_t so = swz128(row, l_seg);
            const size_t g = (rowbase + q0 + row) * D_MODEL + hoff + l_seg * 8;
            cp16(sQh + so, Qhi + g);
            cp16(sQl + so, Qlo + g);
        }
        cp_commit();
    }
    auto load_kv = [&](int kt, int s) {
        const uint32_t sb = sKV + s * FSTG;
        #pragma unroll
        for (int it = 0; it < 4; it++) {
            const int row = l_r0 + it * 16;
            const uint32_t so = swz128(row, l_seg);
            const size_t g = (rowbase + kt + row) * D_MODEL + hoff + l_seg * 8;
            cp16(sb +     0 + so, Khi + g);
            cp16(sb +  8192 + so, Klo + g);
            cp16(sb + 16384 + so, Vhi + g);
            cp16(sb + 24576 + so, Vlo + g);
        }
        cp_commit();
    };

    load_kv(0, 0);
    const bool two = (q0 >= 64);
    if (two) load_kv(64, 1);

    // wait for Q (allow KV groups pending), then load Q fragments
    if (two) cp_wait2(); else cp_wait1();
    __syncthreads();

    uint32_t qah[4][4], qal[4][4];
    {
        const int row = wid * 16 + (lane & 15);
        #pragma unroll
        for (int ks = 0; ks < 4; ks++) {
            const uint32_t so = swz128(row, ks * 2 + (lane >> 4));
            ldm_x4(qah[ks], sQh + so);
            ldm_x4(qal[ks], sQl + so);
        }
    }

    float o[8][4];
    #pragma unroll
    for (int nt = 0; nt < 8; nt++)
        #pragma unroll
        for (int j = 0; j < 4; j++) o[nt][j] = 0.f;
    float m0 = -1e30f, m1 = -1e30f, l0 = 0.f, l1 = 0.f;

    const int r_lo = lane >> 2;            // 0..7
    const int c_lo = (lane & 3) * 2;       // 0,2,4,6
    const int lm   = lane >> 3;            // x4 matrix id
    const int ntl  = lm >> 1, khf = lm & 1;
    const int lr8  = lane & 7;

    for (int kt = 0; kt <= q0; kt += 64) {
        // tile data ready (FIFO groups: at most 1 newer pending)
        if (kt < q0) cp_wait1(); else cp_wait0();
        __syncthreads();
        const uint32_t sb = sKV + ((kt >> 6) & 1) * FSTG;

        // ---- S = Q K^T (3-term) ----
        float s[8][4];
        #pragma unroll
        for (int nt = 0; nt < 8; nt++)
            #pragma unroll
            for (int j = 0; j < 4; j++) s[nt][j] = 0.f;

        #pragma unroll
        for (int ks = 0; ks < 4; ks++) {
            #pragma unroll
            for (int np = 0; np < 4; np++) {
                const int row = (np * 2 + ntl) * 8 + lr8;
                const uint32_t so = swz128(row, ks * 2 + khf);
                uint32_t th[4], tl[4];
                ldm_x4(th, sb + so);            // Khi
                ldm_x4(tl, sb + 8192 + so);     // Klo
                uint32_t bh0[2] = {th[0], th[1]}, bh1[2] = {th[2], th[3]};
                uint32_t bl0[2] = {tl[0], tl[1]}, bl1[2] = {tl[2], tl[3]};
                mma_bf16(s[np*2],   qah[ks], bh0);
                mma_bf16(s[np*2],   qah[ks], bl0);
                mma_bf16(s[np*2],   qal[ks], bh0);
                mma_bf16(s[np*2+1], qah[ks], bh1);
                mma_bf16(s[np*2+1], qah[ks], bl1);
                mma_bf16(s[np*2+1], qal[ks], bh1);
            }
        }

        // ---- scale + causal mask ----
        if (kt == q0) {
            const int row0 = q0 + wid * 16 + r_lo;
            #pragma unroll
            for (int nt = 0; nt < 8; nt++) {
                const int col = kt + nt * 8 + c_lo;
                s[nt][0] = (col     <= row0)     ? s[nt][0] * 0.125f : -1e30f;
                s[nt][1] = (col + 1 <= row0)     ? s[nt][1] * 0.125f : -1e30f;
                s[nt][2] = (col     <= row0 + 8) ? s[nt][2] * 0.125f : -1e30f;
                s[nt][3] = (col + 1 <= row0 + 8) ? s[nt][3] * 0.125f : -1e30f;
            }
        } else {
            #pragma unroll
            for (int nt = 0; nt < 8; nt++)
                #pragma unroll
                for (int j = 0; j < 4; j++) s[nt][j] *= 0.125f;
        }

        // ---- online softmax ----
        float mx0 = -1e30f, mx1 = -1e30f;
        #pragma unroll
        for (int nt = 0; nt < 8; nt++) {
            mx0 = fmaxf(mx0, fmaxf(s[nt][0], s[nt][1]));
            mx1 = fmaxf(mx1, fmaxf(s[nt][2], s[nt][3]));
        }
        mx0 = fmaxf(mx0, shfl_xor_f(mx0, 1)); mx0 = fmaxf(mx0, shfl_xor_f(mx0, 2));
        mx1 = fmaxf(mx1, shfl_xor_f(mx1, 1)); mx1 = fmaxf(mx1, shfl_xor_f(mx1, 2));
        const float mn0 = fmaxf(m0, mx0), mn1 = fmaxf(m1, mx1);
        const float al0 = __expf(m0 - mn0), al1 = __expf(m1 - mn1);
        m0 = mn0; m1 = mn1;
        l0 *= al0; l1 *= al1;
        #pragma unroll
        for (int nt = 0; nt < 8; nt++) {
            o[nt][0] *= al0; o[nt][1] *= al0;
            o[nt][2] *= al1; o[nt][3] *= al1;
        }
        #pragma unroll
        for (int nt = 0; nt < 8; nt++) {
            s[nt][0] = __expf(s[nt][0] - m0);
            s[nt][1] = __expf(s[nt][1] - m0);
            s[nt][2] = __expf(s[nt][2] - m1);
            s[nt][3] = __expf(s[nt][3] - m1);
            l0 += s[nt][0] + s[nt][1];
            l1 += s[nt][2] + s[nt][3];
        }

        // ---- O += P V (3-term) ----
        #pragma unroll
        for (int ks = 0; ks < 4; ks++) {
            uint32_t pah[4], pal[4];
            pack_hl(s[2*ks][0],   s[2*ks][1],   pah[0], pal[0]);
            pack_hl(s[2*ks][2],   s[2*ks][3],   pah[1], pal[1]);
            pack_hl(s[2*ks+1][0], s[2*ks+1][1], pah[2], pal[2]);
            pack_hl(s[2*ks+1][2], s[2*ks+1][3], pah[3], pal[3]);
            #pragma unroll
            for (int np = 0; np < 4; np++) {
                const int row = ks * 16 + khf * 8 + lr8;      // key row
                const int seg = np * 2 + ntl;                 // dim seg
                const uint32_t so = swz128(row, seg);
                uint32_t th[4], tl[4];
                ldm_x4t(th, sb + 16384 + so);   // Vhi
                ldm_x4t(tl, sb + 24576 + so);   // Vlo
                uint32_t bh0[2] = {th[0], th[1]}, bh1[2] = {th[2], th[3]};
                uint32_t bl0[2] = {tl[0], tl[1]}, bl1[2] = {tl[2], tl[3]};
                mma_bf16(o[np*2],   pah, bh0);
                mma_bf16(o[np*2],   pah, bl0);
                mma_bf16(o[np*2],   pal, bh0);
                mma_bf16(o[np*2+1], pah, bh1);
                mma_bf16(o[np*2+1], pah, bl1);
                mma_bf16(o[np*2+1], pal, bh1);
            }
        }

        __syncthreads();                       // stage fully consumed
        if (kt + 128 <= q0) load_kv(kt + 128, (kt >> 6) & 1);
    }

    // ---- epilogue ----
    l0 += shfl_xor_f(l0, 1); l0 += shfl_xor_f(l0, 2);
    l1 += shfl_xor_f(l1, 1); l1 += shfl_xor_f(l1, 2);
    const float inv0 = 1.f / l0, inv1 = 1.f / l1;
    const int row0 = q0 + wid * 16 + r_lo;
    #pragma unroll
    for (int nt = 0; nt < 8; nt++) {
        const int col = hoff + nt * 8 + c_lo;
        uint32_t h0, lo0, h1, lo1;
        pack_hl(o[nt][0] * inv0, o[nt][1] * inv0, h0, lo0);
        pack_hl(o[nt][2] * inv1, o[nt][3] * inv1, h1, lo1);
        const size_t g0 = (rowbase + row0) * D_MODEL + col;
        const size_t g1 = (rowbase + row0 + 8) * D_MODEL + col;
        *(uint32_t*)(Zhi + g0) = h0;
        *(uint32_t*)(Zlo + g0) = lo0;
        *(uint32_t*)(Zhi + g1) = h1;
        *(uint32_t*)(Zlo + g1) = lo1;
    }
}

// ---------------- launch --------------------------------------------------------
extern "C" void kernel_launch(void* const* d_in, const int* in_sizes, int n_in,
                              void* d_out, int out_size) {
    const float* x  = (const float*)d_in[0];
    const float* W[4] = {(const float*)d_in[1], (const float*)d_in[2],
                         (const float*)d_in[3], (const float*)d_in[4]};
    float* out = (float*)d_out;

    void *pxh, *pxl, *pwh, *pwl, *pqh, *pql, *pkh, *pkl, *pvh, *pvl, *pzh, *pzl;
    cudaGetSymbolAddress(&pxh, g_xhi);  cudaGetSymbolAddress(&pxl, g_xlo);
    cudaGetSymbolAddress(&pwh, g_wthi); cudaGetSymbolAddress(&pwl, g_wtlo);
    cudaGetSymbolAddress(&pqh, g_qhi);  cudaGetSymbolAddress(&pql, g_qlo);
    cudaGetSymbolAddress(&pkh, g_khi);  cudaGetSymbolAddress(&pkl, g_klo);
    cudaGetSymbolAddress(&pvh, g_vhi);  cudaGetSymbolAddress(&pvl, g_vlo);
    cudaGetSymbolAddress(&pzh, g_zhi);  cudaGetSymbolAddress(&pzl, g_zlo);

    const size_t wstride = (size_t)D_MODEL * D_MODEL;

    cudaFuncSetAttribute(gemm_mma, cudaFuncAttributeMaxDynamicSharedMemorySize, DYN_SMEM_G);
    cudaFuncSetAttribute(flash_tc, cudaFuncAttributeMaxDynamicSharedMemorySize, DYN_SMEM_F);

    const int n4 = M_ROWS * D_MODEL / 4;
    decomp_kernel<<<(n4 + 255) / 256, 256>>>(x, (bf16*)pxh, (bf16*)pxl, n4);
    dim3 tg(D_MODEL / 32, D_MODEL / 32);
    for (int w = 0; w < 4; w++)
        transdec_kernel<<<tg, dim3(32, 8)>>>(W[w], (bf16*)pwh + w * wstride,
                                             (bf16*)pwl + w * wstride);

    dim3 gg(D_MODEL / 128, M_ROWS / 128);   // (8, 64)
    gemm_mma<<<gg, 256, DYN_SMEM_G>>>((bf16*)pxh, (bf16*)pxl,
                                      (bf16*)pwh + 0 * wstride, (bf16*)pwl + 0 * wstride,
                                      nullptr, (bf16*)pqh, (bf16*)pql);
    gemm_mma<<<gg, 256, DYN_SMEM_G>>>((bf16*)pxh, (bf16*)pxl,
                                      (bf16*)pwh + 1 * wstride, (bf16*)pwl + 1 * wstride,
                                      nullptr, (bf16*)pkh, (bf16*)pkl);
    gemm_mma<<<gg, 256, DYN_SMEM_G>>>((bf16*)pxh, (bf16*)pxl,
                                      (bf16*)pwh + 2 * wstride, (bf16*)pwl + 2 * wstride,
                                      nullptr, (bf16*)pvh, (bf16*)pvl);

    dim3 fg(T_SEQ / 64, (M_ROWS / T_SEQ) * N_HEADS);   // (32, 64)
    flash_tc<<<fg, 128, DYN_SMEM_F>>>((const bf16*)pqh, (const bf16*)pql,
                                      (const bf16*)pkh, (const bf16*)pkl,
                                      (const bf16*)pvh, (const bf16*)pvl,
                                      (bf16*)pzh, (bf16*)pzl);

    gemm_mma<<<gg, 256, DYN_SMEM_G>>>((bf16*)pzh, (bf16*)pzl,
                                      (bf16*)pwh + 3 * wstride, (bf16*)pwl + 3 * wstride,
                                      out, nullptr, nullptr);
}

// round 5
// speedup vs baseline: 4.8590x; 1.2777x over previous
#include <cuda_runtime.h>
#include <cuda_bf16.h>
#include <cuda_fp16.h>
#include <cstdint>
#include <math.h>

#define D_MODEL 1024
#define N_HEADS 16
#define D_HEAD  64
#define T_SEQ   2048
#define M_ROWS  8192

typedef __nv_bfloat16 bf16;

// ---------------- scratch (device globals; no allocation allowed) -------------
__device__ bf16   g_xhi[(size_t)M_ROWS * D_MODEL];
__device__ bf16   g_xlo[(size_t)M_ROWS * D_MODEL];
__device__ bf16   g_wthi[4][(size_t)D_MODEL * D_MODEL];   // W^T, [N][K]
__device__ bf16   g_wtlo[4][(size_t)D_MODEL * D_MODEL];
__device__ bf16   g_qhi[(size_t)M_ROWS * D_MODEL];
__device__ bf16   g_qlo[(size_t)M_ROWS * D_MODEL];
__device__ bf16   g_khi[(size_t)M_ROWS * D_MODEL];
__device__ bf16   g_klo[(size_t)M_ROWS * D_MODEL];
__device__ __half g_vhi[(size_t)M_ROWS * D_MODEL];
__device__ __half g_vlo[(size_t)M_ROWS * D_MODEL];
__device__ bf16   g_zhi[(size_t)M_ROWS * D_MODEL];
__device__ bf16   g_zlo[(size_t)M_ROWS * D_MODEL];

// ---------------- PTX helpers (sm_80-era, valid on compute_103) ----------------
__device__ __forceinline__ uint32_t smem_u32(const void* p) {
    uint32_t a;
    asm("{ .reg .u64 t; cvta.to.shared.u64 t, %1; cvt.u32.u64 %0, t; }" : "=r"(a) : "l"(p));
    return a;
}
__device__ __forceinline__ void cp16(uint32_t dst, const void* src) {
    asm volatile("cp.async.cg.shared.global [%0], [%1], 16;" :: "r"(dst), "l"(src) : "memory");
}
__device__ __forceinline__ void cp_commit() { asm volatile("cp.async.commit_group;" ::: "memory"); }
__device__ __forceinline__ void cp_wait0()  { asm volatile("cp.async.wait_group 0;" ::: "memory"); }
__device__ __forceinline__ void cp_wait1()  { asm volatile("cp.async.wait_group 1;" ::: "memory"); }
__device__ __forceinline__ void cp_wait2()  { asm volatile("cp.async.wait_group 2;" ::: "memory"); }

__device__ __forceinline__ void ldm_x4(uint32_t* r, uint32_t addr) {
    asm volatile("ldmatrix.sync.aligned.m8n8.x4.shared.b16 {%0,%1,%2,%3}, [%4];"
                 : "=r"(r[0]), "=r"(r[1]), "=r"(r[2]), "=r"(r[3]) : "r"(addr));
}
__device__ __forceinline__ void ldm_x4t(uint32_t* r, uint32_t addr) {
    asm volatile("ldmatrix.sync.aligned.m8n8.x4.trans.shared.b16 {%0,%1,%2,%3}, [%4];"
                 : "=r"(r[0]), "=r"(r[1]), "=r"(r[2]), "=r"(r[3]) : "r"(addr));
}
__device__ __forceinline__ void mma_bf16(float* c, const uint32_t* a, const uint32_t* b) {
    asm volatile(
        "mma.sync.aligned.m16n8k16.row.col.f32.bf16.bf16.f32 "
        "{%0,%1,%2,%3}, {%4,%5,%6,%7}, {%8,%9}, {%0,%1,%2,%3};"
        : "+f"(c[0]), "+f"(c[1]), "+f"(c[2]), "+f"(c[3])
        : "r"(a[0]), "r"(a[1]), "r"(a[2]), "r"(a[3]), "r"(b[0]), "r"(b[1]));
}
__device__ __forceinline__ void mma_f16(float* c, const uint32_t* a, const uint32_t* b) {
    asm volatile(
        "mma.sync.aligned.m16n8k16.row.col.f32.f16.f16.f32 "
        "{%0,%1,%2,%3}, {%4,%5,%6,%7}, {%8,%9}, {%0,%1,%2,%3};"
        : "+f"(c[0]), "+f"(c[1]), "+f"(c[2]), "+f"(c[3])
        : "r"(a[0]), "r"(a[1]), "r"(a[2]), "r"(a[3]), "r"(b[0]), "r"(b[1]));
}
__device__ __forceinline__ float shfl_xor_f(float v, int m) {
    return __shfl_xor_sync(0xFFFFFFFF, v, m);
}
__device__ __forceinline__ void pack_hl(float x, float y, uint32_t& h, uint32_t& l) {
    __nv_bfloat162 hh = __floats2bfloat162_rn(x, y);
    __nv_bfloat162 ll = __floats2bfloat162_rn(x - __bfloat162float(hh.x),
                                              y - __bfloat162float(hh.y));
    h = *(uint32_t*)&hh;
    l = *(uint32_t*)&ll;
}
__device__ __forceinline__ void pack_hl16(float x, float y, uint32_t& h, uint32_t& l) {
    __half2 hh = __floats2half2_rn(x, y);
    float2 hf = __half22float2(hh);
    __half2 ll = __floats2half2_rn(x - hf.x, y - hf.y);
    h = *(uint32_t*)&hh;
    l = *(uint32_t*)&ll;
}
__device__ __forceinline__ void pack_h16(float x, float y, uint32_t& h) {
    __half2 hh = __floats2half2_rn(x, y);
    h = *(uint32_t*)&hh;
}

// ================================================================================
// GEMM core: C(128x128 tile) = A @ B^T, split-bf16 3-term, fp32 acc in regs.
// 4 warps (128 thr), warp tile 64x64. 3-stage cp.async, one sync per chunk.
// Stage layout: Ahi@0 Alo@8K Bhi@16K Blo@24K, each 128 rows x 64B (KC=32 bf16).
// ================================================================================
#define KC 32
#define NCHG (D_MODEL / KC)         // 32
#define GSTG 32768
#define DYN_SMEM_G (3 * GSTG + 1024)

__device__ __forceinline__ uint32_t swz64(int row, int kseg) {
    return (uint32_t)(row * 64 + ((kseg ^ ((row >> 1) & 3)) << 4));
}

struct GAcc { float a[4][8][4]; };

__device__ __forceinline__ void gemm_core(
    const bf16* __restrict__ Ahi, const bf16* __restrict__ Alo,
    const bf16* __restrict__ Bhi, const bf16* __restrict__ Blo,
    int rowBase, int colBase, uint32_t base, GAcc& A) {

    const int tid = threadIdx.x;
    const int lane = tid & 31;
    const int wid = tid >> 5;
    const int wm = wid & 1;
    const int wn = wid >> 1;

    const int l_seg = tid & 3;
    const int l_row = tid >> 2;     // 0..31

    auto load_chunk = [&](int c, int s) {
        const uint32_t sb = base + s * GSTG;
        const size_t kof = (size_t)c * KC + l_seg * 8;
        #pragma unroll
        for (int it = 0; it < 4; it++) {
            const int row = l_row + it * 32;
            const uint32_t so = swz64(row, l_seg);
            const size_t aoff = (size_t)(rowBase + row) * D_MODEL + kof;
            const size_t boff = (size_t)(colBase + row) * D_MODEL + kof;
            cp16(sb +     0 + so, Ahi + aoff);
            cp16(sb +  8192 + so, Alo + aoff);
            cp16(sb + 16384 + so, Bhi + boff);
            cp16(sb + 24576 + so, Blo + boff);
        }
        cp_commit();
    };

    #pragma unroll
    for (int i = 0; i < 4; i++)
        #pragma unroll
        for (int j = 0; j < 8; j++)
            #pragma unroll
            for (int k = 0; k < 4; k++) A.a[i][j][k] = 0.f;

    const int g   = lane >> 3;
    const int lr8 = lane & 7;
    const int a_rofs = lr8 + (g & 1) * 8;
    const int a_kofs = g >> 1;
    const int ntl = g >> 1;          // B: which nt of the pair
    const int khf = g & 1;           // B: which k-half

    load_chunk(0, 0);
    load_chunk(1, 1);

    for (int c = 0; c < NCHG; c++) {
        if (c < NCHG - 1) cp_wait1(); else cp_wait0();
        __syncthreads();
        if (c + 2 < NCHG) load_chunk(c + 2, (c + 2) % 3);
        const uint32_t sb = base + (c % 3) * GSTG;

        #pragma unroll
        for (int ks = 0; ks < 2; ks++) {
            uint32_t ah[4][4], al[4][4], bh[8][2], bl[8][2];
            #pragma unroll
            for (int mt = 0; mt < 4; mt++) {
                const int row = wm * 64 + mt * 16 + a_rofs;
                const uint32_t so = swz64(row, ks * 2 + a_kofs);
                ldm_x4(ah[mt], sb + so);
                ldm_x4(al[mt], sb + 8192 + so);
            }
            #pragma unroll
            for (int np = 0; np < 4; np++) {
                const int row = wn * 64 + (np * 2 + ntl) * 8 + lr8;
                const uint32_t so = swz64(row, ks * 2 + khf);
                uint32_t th[4], tl[4];
                ldm_x4(th, sb + 16384 + so);
                ldm_x4(tl, sb + 24576 + so);
                bh[np*2][0] = th[0]; bh[np*2][1] = th[1];
                bh[np*2+1][0] = th[2]; bh[np*2+1][1] = th[3];
                bl[np*2][0] = tl[0]; bl[np*2][1] = tl[1];
                bl[np*2+1][0] = tl[2]; bl[np*2+1][1] = tl[3];
            }
            #pragma unroll
            for (int mt = 0; mt < 4; mt++)
                #pragma unroll
                for (int nt = 0; nt < 8; nt++) {
                    mma_bf16(A.a[mt][nt], ah[mt], bh[nt]);
                    mma_bf16(A.a[mt][nt], ah[mt], bl[nt]);
                    mma_bf16(A.a[mt][nt], al[mt], bh[nt]);
                }
        }
    }
}

// ---- fused QKV projection: z=0 -> Q (bf16 pair), z=1 -> K (bf16 pair),
//      z=2 -> V (fp16 pair) -------------------------------------------------------
__global__ __launch_bounds__(128)
void gemm_qkv(const bf16* __restrict__ xhi, const bf16* __restrict__ xlo,
              const bf16* __restrict__ wthi, const bf16* __restrict__ wtlo,
              bf16* __restrict__ Qh, bf16* __restrict__ Ql,
              bf16* __restrict__ Kh, bf16* __restrict__ Kl,
              __half* __restrict__ Vh, __half* __restrict__ Vl) {
    extern __shared__ __align__(16) char dyn[];
    const uint32_t base = (smem_u32(dyn) + 1023u) & ~1023u;
    const int z = blockIdx.z;
    const size_t ws = (size_t)z * D_MODEL * D_MODEL;
    const int rowBase = blockIdx.y * 128;
    const int colBase = blockIdx.x * 128;

    GAcc acc;
    gemm_core(xhi, xlo, wthi + ws, wtlo + ws, rowBase, colBase, base, acc);

    const int lane = threadIdx.x & 31;
    const int wid = threadIdx.x >> 5;
    const int wm = wid & 1, wn = wid >> 1;
    const int er = lane >> 2;
    const int ec = (lane & 3) * 2;

    #pragma unroll
    for (int mt = 0; mt < 4; mt++) {
        const int r0 = rowBase + wm * 64 + mt * 16 + er;
        #pragma unroll
        for (int nt = 0; nt < 8; nt++) {
            const int cc = colBase + wn * 64 + nt * 8 + ec;
            const size_t g0 = (size_t)r0 * D_MODEL + cc;
            const size_t g1 = (size_t)(r0 + 8) * D_MODEL + cc;
            uint32_t h0, l0, h1, l1;
            if (z == 2) {
                pack_hl16(acc.a[mt][nt][0], acc.a[mt][nt][1], h0, l0);
                pack_hl16(acc.a[mt][nt][2], acc.a[mt][nt][3], h1, l1);
                *(uint32_t*)(Vh + g0) = h0;  *(uint32_t*)(Vl + g0) = l0;
                *(uint32_t*)(Vh + g1) = h1;  *(uint32_t*)(Vl + g1) = l1;
            } else {
                pack_hl(acc.a[mt][nt][0], acc.a[mt][nt][1], h0, l0);
                pack_hl(acc.a[mt][nt][2], acc.a[mt][nt][3], h1, l1);
                bf16* Ch = (z == 0) ? Qh : Kh;
                bf16* Cl = (z == 0) ? Ql : Kl;
                *(uint32_t*)(Ch + g0) = h0;  *(uint32_t*)(Cl + g0) = l0;
                *(uint32_t*)(Ch + g1) = h1;  *(uint32_t*)(Cl + g1) = l1;
            }
        }
    }
}

// ---- output projection: fp32 out -----------------------------------------------
__global__ __launch_bounds__(128)
void gemm_out(const bf16* __restrict__ Ahi, const bf16* __restrict__ Alo,
              const bf16* __restrict__ Bhi, const bf16* __restrict__ Blo,
              float* __restrict__ C) {
    extern __shared__ __align__(16) char dyn[];
    const uint32_t base = (smem_u32(dyn) + 1023u) & ~1023u;
    const int rowBase = blockIdx.y * 128;
    const int colBase = blockIdx.x * 128;

    GAcc acc;
    gemm_core(Ahi, Alo, Bhi, Blo, rowBase, colBase, base, acc);

    const int lane = threadIdx.x & 31;
    const int wid = threadIdx.x >> 5;
    const int wm = wid & 1, wn = wid >> 1;
    const int er = lane >> 2;
    const int ec = (lane & 3) * 2;

    #pragma unroll
    for (int mt = 0; mt < 4; mt++) {
        const int r0 = rowBase + wm * 64 + mt * 16 + er;
        #pragma unroll
        for (int nt = 0; nt < 8; nt++) {
            const int cc = colBase + wn * 64 + nt * 8 + ec;
            *(float2*)(C + (size_t)r0 * D_MODEL + cc) =
                make_float2(acc.a[mt][nt][0], acc.a[mt][nt][1]);
            *(float2*)(C + (size_t)(r0 + 8) * D_MODEL + cc) =
                make_float2(acc.a[mt][nt][2], acc.a[mt][nt][3]);
        }
    }
}

// ---------------- decompose fp32 -> (hi, lo) bf16 ------------------------------
__global__ __launch_bounds__(256)
void decomp_kernel(const float* __restrict__ X, bf16* __restrict__ hi,
                   bf16* __restrict__ lo, int n4) {
    int i = blockIdx.x * 256 + threadIdx.x;
    if (i >= n4) return;
    float4 v = ((const float4*)X)[i];
    uint32_t h0, l0, h1, l1;
    pack_hl(v.x, v.y, h0, l0);
    pack_hl(v.z, v.w, h1, l1);
    ((uint32_t*)hi)[2 * i]     = h0;
    ((uint32_t*)hi)[2 * i + 1] = h1;
    ((uint32_t*)lo)[2 * i]     = l0;
    ((uint32_t*)lo)[2 * i + 1] = l1;
}

// ---------------- transpose + decompose (all 4 weights, grid.z) ----------------
__global__ __launch_bounds__(256)
void transdec_kernel(const float* __restrict__ W0, const float* __restrict__ W1,
                     const float* __restrict__ W2, const float* __restrict__ W3,
                     bf16* __restrict__ thi, bf16* __restrict__ tlo) {
    __shared__ float t[32][33];
    const int w = blockIdx.z;
    const float* W = (w == 0) ? W0 : (w == 1) ? W1 : (w == 2) ? W2 : W3;
    bf16* th = thi + (size_t)w * D_MODEL * D_MODEL;
    bf16* tl = tlo + (size_t)w * D_MODEL * D_MODEL;
    const int n0 = blockIdx.x * 32, k0 = blockIdx.y * 32;
    const int tx = threadIdx.x, ty0 = threadIdx.y;
    #pragma unroll
    for (int j = 0; j < 32; j += 8)
        t[ty0 + j][tx] = W[(size_t)(k0 + ty0 + j) * D_MODEL + n0 + tx];
    __syncthreads();
    #pragma unroll
    for (int j = 0; j < 32; j += 8) {
        const int ty = ty0 + j;
        const float v = t[tx][ty];
        bf16 h = __float2bfloat16(v);
        const size_t o = (size_t)(n0 + ty) * D_MODEL + k0 + tx;
        th[o] = h;
        tl[o] = __float2bfloat16(v - __bfloat162float(h));
    }
}

// ================================================================================
// Tensor-core flash attention (causal). S: 3-term bf16; PV: 2-term fp16.
// CTA: 64 queries of one (b,h); 4 warps x 16 rows; key tiles 64; 3 KV stages.
// smem: Qhi/Qlo 8KB each; stages: Khi,Klo(bf16), Vhi,Vlo(fp16) 8KB each.
// ================================================================================
#define FSTG 32768
#define DYN_SMEM_F (1024 + 16384 + 3 * FSTG)

__device__ __forceinline__ uint32_t swz128(int row, int seg) {
    return (uint32_t)(row * 128 + ((seg ^ (row & 7)) << 4));
}

__global__ __launch_bounds__(128)
void flash_tc(const bf16* __restrict__ Qhi, const bf16* __restrict__ Qlo,
              const bf16* __restrict__ Khi, const bf16* __restrict__ Klo,
              const __half* __restrict__ Vhi, const __half* __restrict__ Vlo,
              bf16* __restrict__ Zhi, bf16* __restrict__ Zlo) {
    extern __shared__ __align__(16) char dyn[];
    const uint32_t base = (smem_u32(dyn) + 1023u) & ~1023u;
    const uint32_t sQh = base, sQl = base + 8192;
    const uint32_t sKV = base + 16384;

    const int bh = blockIdx.y;
    const int b  = bh >> 4;
    const int h  = bh & 15;
    const int qt = gridDim.x - 1 - blockIdx.x;   // heavy CTAs first
    const int q0 = qt * 64;
    const int tid = threadIdx.x;
    const int wid = tid >> 5;
    const int lane = tid & 31;

    const size_t rowbase = (size_t)b * T_SEQ;
    const int hoff = h * D_HEAD;

    const int l_seg = tid & 7, l_r0 = tid >> 3;
    {   // Q tile
        #pragma unroll
        for (int it = 0; it < 4; it++) {
            const int row = l_r0 + it * 16;
            const uint32_t so = swz128(row, l_seg);
            const size_t g = (rowbase + q0 + row) * D_MODEL + hoff + l_seg * 8;
            cp16(sQh + so, Qhi + g);
            cp16(sQl + so, Qlo + g);
        }
        cp_commit();
    }
    auto load_kv = [&](int kt) {
        const uint32_t sb = sKV + ((kt >> 6) % 3) * FSTG;
        #pragma unroll
        for (int it = 0; it < 4; it++) {
            const int row = l_r0 + it * 16;
            const uint32_t so = swz128(row, l_seg);
            const size_t g = (rowbase + kt + row) * D_MODEL + hoff + l_seg * 8;
            cp16(sb +     0 + so, Khi + g);
            cp16(sb +  8192 + so, Klo + g);
            cp16(sb + 16384 + so, Vhi + g);
            cp16(sb + 24576 + so, Vlo + g);
        }
        cp_commit();
    };

    load_kv(0);
    if (q0 >= 64) load_kv(64);

    if (q0 >= 64) cp_wait2(); else cp_wait1();   // Q arrived
    __syncthreads();

    uint32_t qah[4][4], qal[4][4];
    {
        const int row = wid * 16 + (lane & 15);
        #pragma unroll
        for (int ks = 0; ks < 4; ks++) {
            const uint32_t so = swz128(row, ks * 2 + (lane >> 4));
            ldm_x4(qah[ks], sQh + so);
            ldm_x4(qal[ks], sQl + so);
        }
    }

    float o[8][4];
    #pragma unroll
    for (int nt = 0; nt < 8; nt++)
        #pragma unroll
        for (int j = 0; j < 4; j++) o[nt][j] = 0.f;
    float m0 = -1e30f, m1 = -1e30f, l0 = 0.f, l1 = 0.f;

    const int r_lo = lane >> 2;
    const int c_lo = (lane & 3) * 2;
    const int lm   = lane >> 3;
    const int ntl  = lm >> 1, khf = lm & 1;
    const int lr8  = lane & 7;

    for (int kt = 0; kt <= q0; kt += 64) {
        if (kt + 64 <= q0) cp_wait1(); else cp_wait0();
        __syncthreads();
        if (kt + 128 <= q0) load_kv(kt + 128);
        const uint32_t sb = sKV + ((kt >> 6) % 3) * FSTG;

        // ---- S = Q K^T (3-term bf16) ----
        float s[8][4];
        #pragma unroll
        for (int nt = 0; nt < 8; nt++)
            #pragma unroll
            for (int j = 0; j < 4; j++) s[nt][j] = 0.f;

        #pragma unroll
        for (int ks = 0; ks < 4; ks++) {
            #pragma unroll
            for (int np = 0; np < 4; np++) {
                const int row = (np * 2 + ntl) * 8 + lr8;
                const uint32_t so = swz128(row, ks * 2 + khf);
                uint32_t th[4], tl[4];
                ldm_x4(th, sb + so);
                ldm_x4(tl, sb + 8192 + so);
                uint32_t bh0[2] = {th[0], th[1]}, bh1[2] = {th[2], th[3]};
                uint32_t bl0[2] = {tl[0], tl[1]}, bl1[2] = {tl[2], tl[3]};
                mma_bf16(s[np*2],   qah[ks], bh0);
                mma_bf16(s[np*2],   qah[ks], bl0);
                mma_bf16(s[np*2],   qal[ks], bh0);
                mma_bf16(s[np*2+1], qah[ks], bh1);
                mma_bf16(s[np*2+1], qah[ks], bl1);
                mma_bf16(s[np*2+1], qal[ks], bh1);
            }
        }

        // ---- scale + causal mask ----
        if (kt == q0) {
            const int row0 = q0 + wid * 16 + r_lo;
            #pragma unroll
            for (int nt = 0; nt < 8; nt++) {
                const int col = kt + nt * 8 + c_lo;
                s[nt][0] = (col     <= row0)     ? s[nt][0] * 0.125f : -1e30f;
                s[nt][1] = (col + 1 <= row0)     ? s[nt][1] * 0.125f : -1e30f;
                s[nt][2] = (col     <= row0 + 8) ? s[nt][2] * 0.125f : -1e30f;
                s[nt][3] = (col + 1 <= row0 + 8) ? s[nt][3] * 0.125f : -1e30f;
            }
        } else {
            #pragma unroll
            for (int nt = 0; nt < 8; nt++)
                #pragma unroll
                for (int j = 0; j < 4; j++) s[nt][j] *= 0.125f;
        }

        // ---- online softmax ----
        float mx0 = -1e30f, mx1 = -1e30f;
        #pragma unroll
        for (int nt = 0; nt < 8; nt++) {
            mx0 = fmaxf(mx0, fmaxf(s[nt][0], s[nt][1]));
            mx1 = fmaxf(mx1, fmaxf(s[nt][2], s[nt][3]));
        }
        mx0 = fmaxf(mx0, shfl_xor_f(mx0, 1)); mx0 = fmaxf(mx0, shfl_xor_f(mx0, 2));
        mx1 = fmaxf(mx1, shfl_xor_f(mx1, 1)); mx1 = fmaxf(mx1, shfl_xor_f(mx1, 2));
        const float mn0 = fmaxf(m0, mx0), mn1 = fmaxf(m1, mx1);
        const float al0 = __expf(m0 - mn0), al1 = __expf(m1 - mn1);
        m0 = mn0; m1 = mn1;
        l0 *= al0; l1 *= al1;
        #pragma unroll
        for (int nt = 0; nt < 8; nt++) {
            o[nt][0] *= al0; o[nt][1] *= al0;
            o[nt][2] *= al1; o[nt][3] *= al1;
        }
        #pragma unroll
        for (int nt = 0; nt < 8; nt++) {
            s[nt][0] = __expf(s[nt][0] - m0);
            s[nt][1] = __expf(s[nt][1] - m0);
            s[nt][2] = __expf(s[nt][2] - m1);
            s[nt][3] = __expf(s[nt][3] - m1);
            l0 += s[nt][0] + s[nt][1];
            l1 += s[nt][2] + s[nt][3];
        }

        // ---- O += P V (2-term fp16: Ph*Vhi + Ph*Vlo) ----
        #pragma unroll
        for (int ks = 0; ks < 4; ks++) {
            uint32_t pa[4];
            pack_h16(s[2*ks][0],   s[2*ks][1],   pa[0]);
            pack_h16(s[2*ks][2],   s[2*ks][3],   pa[1]);
            pack_h16(s[2*ks+1][0], s[2*ks+1][1], pa[2]);
            pack_h16(s[2*ks+1][2], s[2*ks+1][3], pa[3]);
            #pragma unroll
            for (int np = 0; np < 4; np++) {
                const int row = ks * 16 + khf * 8 + lr8;      // key row
                const int seg = np * 2 + ntl;                 // dim seg
                const uint32_t so = swz128(row, seg);
                uint32_t th[4], tl[4];
                ldm_x4t(th, sb + 16384 + so);   // Vhi (fp16)
                ldm_x4t(tl, sb + 24576 + so);   // Vlo (fp16)
                uint32_t bh0[2] = {th[0], th[1]}, bh1[2] = {th[2], th[3]};
                uint32_t bl0[2] = {tl[0], tl[1]}, bl1[2] = {tl[2], tl[3]};
                mma_f16(o[np*2],   pa, bh0);
                mma_f16(o[np*2],   pa, bl0);
                mma_f16(o[np*2+1], pa, bh1);
                mma_f16(o[np*2+1], pa, bl1);
            }
        }
    }

    // ---- epilogue ----
    l0 += shfl_xor_f(l0, 1); l0 += shfl_xor_f(l0, 2);
    l1 += shfl_xor_f(l1, 1); l1 += shfl_xor_f(l1, 2);
    const float inv0 = 1.f / l0, inv1 = 1.f / l1;
    const int row0 = q0 + wid * 16 + r_lo;
    #pragma unroll
    for (int nt = 0; nt < 8; nt++) {
        const int col = hoff + nt * 8 + c_lo;
        uint32_t h0, lo0, h1, lo1;
        pack_hl(o[nt][0] * inv0, o[nt][1] * inv0, h0, lo0);
        pack_hl(o[nt][2] * inv1, o[nt][3] * inv1, h1, lo1);
        const size_t g0 = (rowbase + row0) * D_MODEL + col;
        const size_t g1 = (rowbase + row0 + 8) * D_MODEL + col;
        *(uint32_t*)(Zhi + g0) = h0;
        *(uint32_t*)(Zlo + g0) = lo0;
        *(uint32_t*)(Zhi + g1) = h1;
        *(uint32_t*)(Zlo + g1) = lo1;
    }
}

// ---------------- launch --------------------------------------------------------
extern "C" void kernel_launch(void* const* d_in, const int* in_sizes, int n_in,
                              void* d_out, int out_size) {
    const float* x = (const float*)d_in[0];
    float* out = (float*)d_out;

    void *pxh, *pxl, *pwh, *pwl, *pqh, *pql, *pkh, *pkl, *pvh, *pvl, *pzh, *pzl;
    cudaGetSymbolAddress(&pxh, g_xhi);  cudaGetSymbolAddress(&pxl, g_xlo);
    cudaGetSymbolAddress(&pwh, g_wthi); cudaGetSymbolAddress(&pwl, g_wtlo);
    cudaGetSymbolAddress(&pqh, g_qhi);  cudaGetSymbolAddress(&pql, g_qlo);
    cudaGetSymbolAddress(&pkh, g_khi);  cudaGetSymbolAddress(&pkl, g_klo);
    cudaGetSymbolAddress(&pvh, g_vhi);  cudaGetSymbolAddress(&pvl, g_vlo);
    cudaGetSymbolAddress(&pzh, g_zhi);  cudaGetSymbolAddress(&pzl, g_zlo);

    const size_t wstride = (size_t)D_MODEL * D_MODEL;

    cudaFuncSetAttribute(gemm_qkv, cudaFuncAttributeMaxDynamicSharedMemorySize, DYN_SMEM_G);
    cudaFuncSetAttribute(gemm_out, cudaFuncAttributeMaxDynamicSharedMemorySize, DYN_SMEM_G);
    cudaFuncSetAttribute(flash_tc, cudaFuncAttributeMaxDynamicSharedMemorySize, DYN_SMEM_F);

    const int n4 = M_ROWS * D_MODEL / 4;
    decomp_kernel<<<(n4 + 255) / 256, 256>>>(x, (bf16*)pxh, (bf16*)pxl, n4);
    dim3 tg(D_MODEL / 32, D_MODEL / 32, 4);
    transdec_kernel<<<tg, dim3(32, 8)>>>((const float*)d_in[1], (const float*)d_in[2],
                                         (const float*)d_in[3], (const float*)d_in[4],
                                         (bf16*)pwh, (bf16*)pwl);

    dim3 gq(D_MODEL / 128, M_ROWS / 128, 3);   // (8, 64, 3)
    gemm_qkv<<<gq, 128, DYN_SMEM_G>>>((bf16*)pxh, (bf16*)pxl,
                                      (bf16*)pwh, (bf16*)pwl,
                                      (bf16*)pqh, (bf16*)pql,
                                      (bf16*)pkh, (bf16*)pkl,
                                      (__half*)pvh, (__half*)pvl);

    dim3 fg(T_SEQ / 64, (M_ROWS / T_SEQ) * N_HEADS);   // (32, 64)
    flash_tc<<<fg, 128, DYN_SMEM_F>>>((const bf16*)pqh, (const bf16*)pql,
                                      (const bf16*)pkh, (const bf16*)pkl,
                                      (const __half*)pvh, (const __half*)pvl,
                                      (bf16*)pzh, (bf16*)pzl);

    dim3 go(D_MODEL / 128, M_ROWS / 128);   // (8, 64)
    gemm_out<<<go, 128, DYN_SMEM_G>>>((bf16*)pzh, (bf16*)pzl,
                                      (bf16*)pwh + 3 * wstride, (bf16*)pwl + 3 * wstride,
                                      out);
}